// round 2
// baseline (speedup 1.0000x reference)
#include <cuda_runtime.h>

#define N_TOTAL   100000
#define FEAT      128
#define NB_ROWS   50000
#define KNEI      16
#define EMB       128
#define RTILE     128
#define TPB       256
#define NBLK      ((NB_ROWS + RTILE - 1) / RTILE)   // 391
#define SMEM_BYTES (2 * FEAT * EMB * 4)             // 131072

// Scratch (allocation-free rule: __device__ globals)
__device__ float g_psum[NBLK * EMB];
__device__ float g_psq [NBLK * EMB];
__device__ float g_scale[EMB];
__device__ float g_bias [EMB];

// ---- packed f32x2 helpers (Blackwell) ----
__device__ __forceinline__ unsigned long long pack2(float x) {
    unsigned long long r;
    asm("mov.b64 %0, {%1, %1};" : "=l"(r) : "r"(__float_as_uint(x)));
    return r;
}
__device__ __forceinline__ void fma2(unsigned long long& d,
                                     unsigned long long a,
                                     unsigned long long b) {
    asm("fma.rn.f32x2 %0, %1, %2, %0;" : "+l"(d) : "l"(a), "l"(b));
}
__device__ __forceinline__ void unpack2(unsigned long long v, float& lo, float& hi) {
    unsigned int l, h;
    asm("mov.b64 {%0, %1}, %2;" : "=r"(l), "=r"(h) : "l"(v));
    lo = __uint_as_float(l);
    hi = __uint_as_float(h);
}

// ============================================================================
// Kernel A: gather-mean + GEMM + per-block column sum/sumsq partials.
// Writes pre-BN x into `out`.
// ============================================================================
__global__ void __launch_bounds__(TPB)
fused_a(const float* __restrict__ raw,
        const float* __restrict__ W,
        const int* __restrict__ nidx,          // int32 (JAX x64 disabled)
        float* __restrict__ out)
{
    extern __shared__ float smem[];
    float* s_w   = smem;              // [128][128] weight, row k contiguous
    float* s_agg = smem + FEAT * EMB; // [128][128] aggregated features

    const int tid = threadIdx.x;
    const int bid = blockIdx.x;
    const int rowBase = bid * RTILE;

    // --- load weight to smem (16384 floats) ---
    {
        const float4* Wv = (const float4*)W;
        float4* sv = (float4*)s_w;
        for (int i = tid; i < FEAT * EMB / 4; i += TPB) sv[i] = Wv[i];
    }

    // --- gather + mean: each warp owns 16 rows; lane covers 4 cols (float4) ---
    {
        const int warp = tid >> 5, lane = tid & 31;
        for (int i = 0; i < 16; i++) {
            const int rl = warp * 16 + i;
            const int rg = rowBase + rl;
            float4 acc = make_float4(0.f, 0.f, 0.f, 0.f);
            if (rg < NB_ROWS) {
                int my = 0;
                if (lane < KNEI) my = nidx[rg * KNEI + lane];
                #pragma unroll
                for (int k = 0; k < KNEI; k++) {
                    const int id = __shfl_sync(0xffffffffu, my, k);
                    const float4 v =
                        ((const float4*)(raw + (long long)id * FEAT))[lane];
                    acc.x += v.x; acc.y += v.y; acc.z += v.z; acc.w += v.w;
                }
                const float inv = 1.0f / KNEI;
                acc.x *= inv; acc.y *= inv; acc.z *= inv; acc.w *= inv;
            }
            ((float4*)(s_agg + rl * FEAT))[lane] = acc;
        }
    }
    __syncthreads();

    // --- GEMM: thread (ty,tx) computes rows ty*8..+7, column pairs tx*2+32*j ---
    const int tx = tid & 15, ty = tid >> 4;
    unsigned long long acc[8][4];
    #pragma unroll
    for (int i = 0; i < 8; i++)
        #pragma unroll
        for (int j = 0; j < 4; j++) acc[i][j] = 0ULL;

    #pragma unroll 4
    for (int k = 0; k < FEAT; k++) {
        unsigned long long aa[8];
        #pragma unroll
        for (int i = 0; i < 8; i++)
            aa[i] = pack2(s_agg[(ty * 8 + i) * FEAT + k]);
        unsigned long long bb[4];
        #pragma unroll
        for (int j = 0; j < 4; j++)
            bb[j] = *(const unsigned long long*)(s_w + k * EMB + tx * 2 + 32 * j);
        #pragma unroll
        for (int i = 0; i < 8; i++)
            #pragma unroll
            for (int j = 0; j < 4; j++)
                fma2(acc[i][j], aa[i], bb[j]);
    }

    // --- write pre-BN x ---
    #pragma unroll
    for (int i = 0; i < 8; i++) {
        const int rg = rowBase + ty * 8 + i;
        if (rg < NB_ROWS) {
            #pragma unroll
            for (int j = 0; j < 4; j++)
                *(unsigned long long*)(out + (long long)rg * EMB + tx * 2 + 32 * j)
                    = acc[i][j];
        }
    }

    __syncthreads();   // all GEMM reads of s_agg complete before reuse

    // --- column sum / sumsq partials (rows beyond NB_ROWS contribute exact 0) ---
    float* s_sum = s_agg;          // [16][128]
    float* s_sq  = s_agg + 2048;   // [16][128]
    #pragma unroll
    for (int j = 0; j < 4; j++) {
        float s0 = 0.f, s1 = 0.f, q0 = 0.f, q1 = 0.f;
        #pragma unroll
        for (int i = 0; i < 8; i++) {
            float x0, x1;
            unpack2(acc[i][j], x0, x1);
            s0 += x0; q0 += x0 * x0;
            s1 += x1; q1 += x1 * x1;
        }
        const int c = tx * 2 + 32 * j;
        s_sum[ty * 128 + c]     = s0;
        s_sum[ty * 128 + c + 1] = s1;
        s_sq [ty * 128 + c]     = q0;
        s_sq [ty * 128 + c + 1] = q1;
    }
    __syncthreads();

    if (tid < 128) {
        float s = 0.f, q = 0.f;
        #pragma unroll
        for (int t = 0; t < 16; t++) {
            s += s_sum[t * 128 + tid];
            q += s_sq [t * 128 + tid];
        }
        g_psum[bid * 128 + tid] = s;
        g_psq [bid * 128 + tid] = q;
    }
}

// ============================================================================
// Kernel B: finalize per-column scale/bias (deterministic sequential reduce).
// ============================================================================
__global__ void stats_b(const float* __restrict__ gamma,
                        const float* __restrict__ beta)
{
    const int c = threadIdx.x;
    float s = 0.f, q = 0.f;
    for (int b = 0; b < NBLK; b++) {
        s += g_psum[b * 128 + c];
        q += g_psq [b * 128 + c];
    }
    const float invN = 1.0f / (float)NB_ROWS;
    const float mean = s * invN;
    const float var  = q * invN - mean * mean;
    const float sc   = gamma[c] * rsqrtf(var + 1e-5f);
    g_scale[c] = sc;
    g_bias [c] = beta[c] - mean * sc;
}

// ============================================================================
// Kernel C: in-place BN apply + LeakyReLU (vectorized float4).
// ============================================================================
__global__ void __launch_bounds__(256)
bn_c(float* __restrict__ out)
{
    const int i = blockIdx.x * blockDim.x + threadIdx.x;       // float4 index
    if (i >= NB_ROWS * EMB / 4) return;
    float4 v = ((float4*)out)[i];
    const int c4 = i & 31;                                     // 128/4 = 32
    const float4 sc = ((const float4*)g_scale)[c4];
    const float4 bs = ((const float4*)g_bias)[c4];
    float x;
    x = v.x * sc.x + bs.x; v.x = (x >= 0.f) ? x : 0.01f * x;
    x = v.y * sc.y + bs.y; v.y = (x >= 0.f) ? x : 0.01f * x;
    x = v.z * sc.z + bs.z; v.z = (x >= 0.f) ? x : 0.01f * x;
    x = v.w * sc.w + bs.w; v.w = (x >= 0.f) ? x : 0.01f * x;
    ((float4*)out)[i] = v;
}

// ============================================================================
extern "C" void kernel_launch(void* const* d_in, const int* in_sizes, int n_in,
                              void* d_out, int out_size)
{
    const float* raw   = (const float*)d_in[0];
    const float* W     = (const float*)d_in[1];
    const float* gamma = (const float*)d_in[2];
    const float* beta  = (const float*)d_in[3];
    const int*   nidx  = (const int*)d_in[4];
    float* out = (float*)d_out;

    cudaFuncSetAttribute(fused_a, cudaFuncAttributeMaxDynamicSharedMemorySize,
                         SMEM_BYTES);

    fused_a<<<NBLK, TPB, SMEM_BYTES>>>(raw, W, nidx, out);
    stats_b<<<1, 128>>>(gamma, beta);
    const int n4 = NB_ROWS * EMB / 4;
    bn_c<<<(n4 + 255) / 256, 256>>>(out);
}

// round 3
// speedup vs baseline: 1.2257x; 1.2257x over previous
#include <cuda_runtime.h>

#define N_TOTAL   100000
#define FEAT      128
#define NB_ROWS   50000
#define KNEI      16
#define EMB       128
#define RTILE     64
#define TPB       256
#define NBLK      ((NB_ROWS + RTILE - 1) / RTILE)   // 782
#define AGG_LD    132                               // padded row stride (floats)
#define SMEM_BYTES ((FEAT * EMB + RTILE * AGG_LD) * 4)   // 65536 + 33792 = 99328

typedef unsigned long long ull;

// Scratch (allocation-free rule: __device__ globals)
__device__ float g_psum[NBLK * EMB];
__device__ float g_psq [NBLK * EMB];
__device__ float g_scale[EMB];
__device__ float g_bias [EMB];

// ---- packed f32x2 helpers (Blackwell) ----
__device__ __forceinline__ ull pack2(float x) {
    ull r;
    asm("mov.b64 %0, {%1, %1};" : "=l"(r) : "r"(__float_as_uint(x)));
    return r;
}
__device__ __forceinline__ void fma2(ull& d, ull a, ull b) {
    asm("fma.rn.f32x2 %0, %1, %2, %0;" : "+l"(d) : "l"(a), "l"(b));
}
__device__ __forceinline__ void unpack2(ull v, float& lo, float& hi) {
    unsigned int l, h;
    asm("mov.b64 {%0, %1}, %2;" : "=r"(l), "=r"(h) : "l"(v));
    lo = __uint_as_float(l);
    hi = __uint_as_float(h);
}

// ============================================================================
// Kernel A: gather-mean + GEMM + per-block column sum/sumsq partials.
// 64-row tile, 97KB smem -> 2 CTAs/SM.
// ============================================================================
__global__ void __launch_bounds__(TPB, 2)
fused_a(const float* __restrict__ raw,
        const float* __restrict__ W,
        const int* __restrict__ nidx,
        float* __restrict__ out)
{
    extern __shared__ float smem[];
    float* s_w   = smem;              // [128][128] weight, row k contiguous
    float* s_agg = smem + FEAT * EMB; // [64][AGG_LD] aggregated features

    const int tid = threadIdx.x;
    const int bid = blockIdx.x;
    const int rowBase = bid * RTILE;

    // --- load weight to smem (16384 floats) ---
    {
        const float4* Wv = (const float4*)W;
        float4* sv = (float4*)s_w;
        for (int i = tid; i < FEAT * EMB / 4; i += TPB) sv[i] = Wv[i];
    }

    // --- gather + mean: each warp owns 8 rows; lane covers 4 cols (float4) ---
    {
        const int warp = tid >> 5, lane = tid & 31;
        #pragma unroll
        for (int i = 0; i < 8; i++) {
            const int rl = warp * 8 + i;
            const int rg = rowBase + rl;
            float4 acc = make_float4(0.f, 0.f, 0.f, 0.f);
            if (rg < NB_ROWS) {
                int my = 0;
                if (lane < KNEI) my = nidx[rg * KNEI + lane];
                #pragma unroll
                for (int k = 0; k < KNEI; k++) {
                    const int id = __shfl_sync(0xffffffffu, my, k);
                    const float4 v =
                        ((const float4*)(raw + (long long)id * FEAT))[lane];
                    acc.x += v.x; acc.y += v.y; acc.z += v.z; acc.w += v.w;
                }
                const float inv = 1.0f / KNEI;
                acc.x *= inv; acc.y *= inv; acc.z *= inv; acc.w *= inv;
            }
            ((float4*)(s_agg + rl * AGG_LD))[lane] = acc;
        }
    }
    __syncthreads();

    // --- GEMM: thread (ty,tx): rows ty*4..+3, cols tx*4..+3 and 64+tx*4..+3 ---
    const int tx = tid & 15, ty = tid >> 4;
    ull acc[4][4];
    #pragma unroll
    for (int i = 0; i < 4; i++)
        #pragma unroll
        for (int j = 0; j < 4; j++) acc[i][j] = 0ULL;

    const float* aBase = s_agg + (ty * 4) * AGG_LD;
    const float* bBase = s_w + tx * 4;

    #pragma unroll 2
    for (int k0 = 0; k0 < FEAT; k0 += 4) {
        float4 a[4];
        #pragma unroll
        for (int i = 0; i < 4; i++)
            a[i] = *(const float4*)(aBase + i * AGG_LD + k0);

        #pragma unroll
        for (int kk = 0; kk < 4; kk++) {
            const ulonglong2 b0 =
                *(const ulonglong2*)(bBase + (k0 + kk) * EMB);
            const ulonglong2 b1 =
                *(const ulonglong2*)(bBase + (k0 + kk) * EMB + 64);
            #pragma unroll
            for (int i = 0; i < 4; i++) {
                const float as = (kk == 0) ? a[i].x : (kk == 1) ? a[i].y
                               : (kk == 2) ? a[i].z : a[i].w;
                const ull av = pack2(as);
                fma2(acc[i][0], av, b0.x);
                fma2(acc[i][1], av, b0.y);
                fma2(acc[i][2], av, b1.x);
                fma2(acc[i][3], av, b1.y);
            }
        }
    }

    // --- write pre-BN x (two 16B stores per row) ---
    #pragma unroll
    for (int i = 0; i < 4; i++) {
        const int rg = rowBase + ty * 4 + i;
        if (rg < NB_ROWS) {
            ulonglong2 v0; v0.x = acc[i][0]; v0.y = acc[i][1];
            ulonglong2 v1; v1.x = acc[i][2]; v1.y = acc[i][3];
            *(ulonglong2*)(out + (long long)rg * EMB + tx * 4)      = v0;
            *(ulonglong2*)(out + (long long)rg * EMB + 64 + tx * 4) = v1;
        }
    }

    __syncthreads();   // GEMM reads of s_agg done before reuse

    // --- column sum / sumsq partials (invalid rows contributed exact 0) ---
    float* s_sum = s_agg;          // [16][128]
    float* s_sq  = s_agg + 2048;   // [16][128]
    #pragma unroll
    for (int j = 0; j < 4; j++) {
        float s0 = 0.f, s1 = 0.f, q0 = 0.f, q1 = 0.f;
        #pragma unroll
        for (int i = 0; i < 4; i++) {
            float x0, x1;
            unpack2(acc[i][j], x0, x1);
            s0 += x0; q0 += x0 * x0;
            s1 += x1; q1 += x1 * x1;
        }
        const int c = (j < 2) ? (tx * 4 + 2 * j) : (64 + tx * 4 + 2 * (j - 2));
        s_sum[ty * 128 + c]     = s0;
        s_sum[ty * 128 + c + 1] = s1;
        s_sq [ty * 128 + c]     = q0;
        s_sq [ty * 128 + c + 1] = q1;
    }
    __syncthreads();

    if (tid < 128) {
        float s = 0.f, q = 0.f;
        #pragma unroll
        for (int t = 0; t < 16; t++) {
            s += s_sum[t * 128 + tid];
            q += s_sq [t * 128 + tid];
        }
        g_psum[bid * 128 + tid] = s;
        g_psq [bid * 128 + tid] = q;
    }
}

// ============================================================================
// Kernel B: finalize per-column scale/bias. 512 threads, 4-way deterministic
// split per column, then fixed-order combine.
// ============================================================================
__global__ void __launch_bounds__(512)
stats_b(const float* __restrict__ gamma,
        const float* __restrict__ beta)
{
    __shared__ float sh_s[4][128];
    __shared__ float sh_q[4][128];
    const int c = threadIdx.x & 127;
    const int p = threadIdx.x >> 7;           // 0..3
    float s = 0.f, q = 0.f;
    for (int b = p; b < NBLK; b += 4) {
        s += g_psum[b * 128 + c];
        q += g_psq [b * 128 + c];
    }
    sh_s[p][c] = s;
    sh_q[p][c] = q;
    __syncthreads();
    if (threadIdx.x < 128) {
        float ss = ((sh_s[0][c] + sh_s[1][c]) + (sh_s[2][c] + sh_s[3][c]));
        float qq = ((sh_q[0][c] + sh_q[1][c]) + (sh_q[2][c] + sh_q[3][c]));
        const float invN = 1.0f / (float)NB_ROWS;
        const float mean = ss * invN;
        const float var  = qq * invN - mean * mean;
        const float sc   = gamma[c] * rsqrtf(var + 1e-5f);
        g_scale[c] = sc;
        g_bias [c] = beta[c] - mean * sc;
    }
}

// ============================================================================
// Kernel C: in-place BN apply + LeakyReLU (vectorized float4).
// ============================================================================
__global__ void __launch_bounds__(256)
bn_c(float* __restrict__ out)
{
    const int i = blockIdx.x * blockDim.x + threadIdx.x;       // float4 index
    if (i >= NB_ROWS * EMB / 4) return;
    float4 v = ((float4*)out)[i];
    const int c4 = i & 31;                                     // 128/4 = 32
    const float4 sc = ((const float4*)g_scale)[c4];
    const float4 bs = ((const float4*)g_bias)[c4];
    float x;
    x = v.x * sc.x + bs.x; v.x = (x >= 0.f) ? x : 0.01f * x;
    x = v.y * sc.y + bs.y; v.y = (x >= 0.f) ? x : 0.01f * x;
    x = v.z * sc.z + bs.z; v.z = (x >= 0.f) ? x : 0.01f * x;
    x = v.w * sc.w + bs.w; v.w = (x >= 0.f) ? x : 0.01f * x;
    ((float4*)out)[i] = v;
}

// ============================================================================
extern "C" void kernel_launch(void* const* d_in, const int* in_sizes, int n_in,
                              void* d_out, int out_size)
{
    const float* raw   = (const float*)d_in[0];
    const float* W     = (const float*)d_in[1];
    const float* gamma = (const float*)d_in[2];
    const float* beta  = (const float*)d_in[3];
    const int*   nidx  = (const int*)d_in[4];
    float* out = (float*)d_out;

    cudaFuncSetAttribute(fused_a, cudaFuncAttributeMaxDynamicSharedMemorySize,
                         SMEM_BYTES);

    fused_a<<<NBLK, TPB, SMEM_BYTES>>>(raw, W, nidx, out);
    stats_b<<<1, 512>>>(gamma, beta);
    const int n4 = NB_ROWS * EMB / 4;
    bn_c<<<(n4 + 255) / 256, 256>>>(out);
}